// round 15
// baseline (speedup 1.0000x reference)
#include <cuda_runtime.h>
#include <math.h>

#define B_  64
#define T_  512
#define I_  1024
#define H_  1024
#define M_  (B_*T_)

typedef unsigned long long ull;

// ---------------------------------------------------------------------------
// f32x2 packed helpers (sm_103a FFMA2/FADD2 — only reachable via PTX)
// ---------------------------------------------------------------------------
__device__ __forceinline__ ull ffma2(ull a, ull b, ull c) {
    ull d;
    asm("fma.rn.f32x2 %0, %1, %2, %3;" : "=l"(d) : "l"(a), "l"(b), "l"(c));
    return d;
}
__device__ __forceinline__ ull fadd2(ull a, ull b) {
    ull d;
    asm("add.rn.f32x2 %0, %1, %2;" : "=l"(d) : "l"(a), "l"(b));
    return d;
}
__device__ __forceinline__ ull splat2(float x) {
    ull r;
    asm("mov.b64 %0, {%1, %1};" : "=l"(r) : "f"(x));
    return r;
}

// ---------------------------------------------------------------------------
// Scratch (device globals — no allocation allowed)
// ---------------------------------------------------------------------------
__device__ float g_xt[T_][I_][B_];     // transposed x: [t][k][b]  (128 MB)
__device__ float g_ht[2][H_][B_];      // transposed h double buffer [buf][k][b]
__device__ unsigned g_flag[2][64 * 8]; // per-block progress flags (32B apart),
                                       // monotonic across graph replays

#define SCAN_BLOCKS  128
#define GROUP_BLOCKS 64
#define NTHREADS     512

// ---------------------------------------------------------------------------
// Kernel T: transpose x[b][t][i] -> g_xt[t][i][b]. 32x32 tiles.
// ---------------------------------------------------------------------------
__global__ __launch_bounds__(256)
void transpose_x_kernel(const float* __restrict__ x) {
    __shared__ float tile[32][33];
    const int tx = threadIdx.x;
    const int ty = threadIdx.y;
    const int i0 = blockIdx.x * 32;
    const int b0 = blockIdx.y * 32;
    const int t  = blockIdx.z;

#pragma unroll
    for (int r = ty; r < 32; r += 8)
        tile[r][tx] = x[(size_t)(b0 + r) * T_ * I_ + (size_t)t * I_ + i0 + tx];
    __syncthreads();
#pragma unroll
    for (int r = ty; r < 32; r += 8)
        g_xt[t][i0 + r][b0 + tx] = tile[tx][r];
}

// ---------------------------------------------------------------------------
// Kernel S: fused persistent scan — 512 threads (4 warps/SMSP for latency
// hiding), merged X/H accumulation, distributed release/acquire flags.
//
// 128 blocks, 1/SM. Block (bh, cg): batches [bh*32,+32), cols [cg*16,+16).
// Warp w (16): wk=w&7 -> k-slice [wk*128,+128); wc=w>>3 -> col half (8 cols).
// Lane l: k4=l>>3 (32-k sub-slice), cgl=(l>>2)&1 (4-col quad), bg=l&3
// (8 batches). Lane tile: 8b x 4c = 16 f32x2 accumulators.
//
// U_t/W_t smem layout: [k][16], stride 16 floats, with per-row QUAD ROTATION
// phys_quad = (quad + (k>>5)) & 3. Inside a lane's k-slice (k>>5)&3 == k4, so
// the rotated quad is a compile-time constant per lane: (wc*2+cgl+k4)&3.
// Result: the 8 lane-groups of an LDS.128 spread over 4 quads 2x each ->
// 2-way conflict (was 4-way), zero extra address math.
//
// Per step tau (one reduction):
//   X-kloop (acc = W x_tau, barrier-independent) -> flag wait -> H-kloop
//   (acc += U h_{tau-1}) -> shfl(k4) + smem(wk) reduce -> owner thread
//   (c=warp, b=lane; 1 output/thread) 8-way sum + tanh -> g_ht + C_f ->
//   release -> coalesced out1 store.
// ---------------------------------------------------------------------------
#define KT_STRIDE 16
#define KT_FLOATS (H_ * KT_STRIDE)                  // 16384 floats = 64 KB
#define RED_OFF   (2 * KT_FLOATS)                   // 32768
#define RED_FLOATS (8 * 512)                        // 16 KB
#define CF_OFF    (RED_OFF + RED_FLOATS)            // 36864
#define CF_STRIDE 33
#define CF_FLOATS (16 * CF_STRIDE + 16)             // padded
#define BASE_OFF  (CF_OFF + CF_FLOATS)
#define SCAN_SMEM ((BASE_OFF + 8) * sizeof(float))  // ~146.4 KB

__global__ __launch_bounds__(NTHREADS, 1)
void scan_kernel(float* __restrict__ out, const float* __restrict__ U,
                 const float* __restrict__ bU, const float* __restrict__ W,
                 const float* __restrict__ bW) {
    extern __shared__ float smem[];
    float* U_t = smem;                  // [1024][16] quad-rotated
    float* W_t = smem + KT_FLOATS;      // [1024][16] quad-rotated
    float* red = smem + RED_OFF;        // [8][512]   [wk][c*32+b]
    float* C_f = smem + CF_OFF;         // [16][33]

    const int tid = threadIdx.x;
    const int l   = tid & 31;
    const int w   = tid >> 5;            // 0..15
    const int wk  = w & 7;
    const int wc  = w >> 3;              // 0..1
    const int bh  = blockIdx.x & 1;
    const int cg  = blockIdx.x >> 1;     // 0..63
    const int k4  = l >> 3;
    const int cgl = (l >> 2) & 1;
    const int bg  = l & 3;
    const int kbase = wk * 128 + k4 * 32;
    const int physq = (wc * 2 + cgl + k4) & 3;   // rotated quad, cmp-time const

    // entry: read my OWN flag (only I write it) -> replay-safe base
    if (tid == 0) {
        unsigned v;
        asm volatile("ld.acquire.gpu.global.u32 %0, [%1];"
                     : "=r"(v) : "l"(&g_flag[bh][cg * 8]) : "memory");
        *(unsigned*)&smem[BASE_OFF] = v;
    }

    // one-time: transpose U/W slices into quad-rotated smem layout
    for (int idx = tid; idx < 16 * H_; idx += NTHREADS) {
        int c = idx >> 10;                // 0..15 (logical col)
        int k = idx & (H_ - 1);
        int pc = ((((c >> 2) + (k >> 5)) & 3) << 2) | (c & 3);
        U_t[k * KT_STRIDE + pc] = U[(size_t)(cg * 16 + c) * H_ + k];
        W_t[k * KT_STRIDE + pc] = W[(size_t)(cg * 16 + c) * I_ + k];
    }
    // owner thread (c = w, b = l) bias
    const float bWc = bW[cg * 16 + w];
    const float bSc = bWc + bU[cg * 16 + w];
    __syncthreads();
    const unsigned base_r = *(const unsigned*)&smem[BASE_OFF];

    const float* urow0 = U_t + kbase * KT_STRIDE + physq * 4;
    const float* wrow0 = W_t + kbase * KT_STRIDE + physq * 4;
    const int bB  = bh * 32 + bg * 8;
    // out-store mapping
    const int b9 = tid >> 4;             // 0..31
    const int c9 = tid & 15;             // 0..15
    float* o9 = out + (size_t)(bh * 32 + b9) * T_ * H_ + cg * 16 + c9;

    ull acc[4][4];

// ---- macro: accumulate one k-slice matvec into acc ------------------------
#define KLOOP(SRCROW, UWROW)                                                  \
    {                                                                         \
        const float* srow_ = (SRCROW);                                        \
        const float* mrow_ = (UWROW);                                         \
        _Pragma("unroll 8")                                                   \
        for (int i = 0; i < 32; ++i) {                                        \
            const ulonglong2* hp = (const ulonglong2*)(srow_ + i * B_);       \
            ulonglong2 hA = __ldcg(hp);                                       \
            ulonglong2 hB = __ldcg(hp + 1);                                   \
            float4 u0 = *(const float4*)(mrow_ + i * KT_STRIDE);              \
            float uf[4] = {u0.x, u0.y, u0.z, u0.w};                           \
            _Pragma("unroll")                                                 \
            for (int c = 0; c < 4; ++c) {                                     \
                ull s = splat2(uf[c]);                                        \
                acc[c][0] = ffma2(hA.x, s, acc[c][0]);                        \
                acc[c][1] = ffma2(hA.y, s, acc[c][1]);                        \
                acc[c][2] = ffma2(hB.x, s, acc[c][2]);                        \
                acc[c][3] = ffma2(hB.y, s, acc[c][3]);                        \
            }                                                                 \
        }                                                                     \
    }

// ---- macro: in-warp butterfly (k4) + smem partials (wk) -------------------
#define REDUCE_TO_SMEM()                                                      \
    {                                                                         \
        _Pragma("unroll")                                                     \
        for (int c = 0; c < 4; ++c)                                           \
            _Pragma("unroll")                                                 \
            for (int p = 0; p < 4; ++p) {                                     \
                acc[c][p] = fadd2(acc[c][p],                                  \
                    __shfl_xor_sync(0xffffffffu, acc[c][p], 8));              \
                acc[c][p] = fadd2(acc[c][p],                                  \
                    __shfl_xor_sync(0xffffffffu, acc[c][p], 16));             \
            }                                                                 \
        if (l < 8) {                                                          \
            float* rw = red + wk * 512 + (wc * 8 + cgl * 4) * 32 + bg * 8;    \
            _Pragma("unroll")                                                 \
            for (int c = 0; c < 4; ++c)                                       \
                _Pragma("unroll")                                             \
                for (int p = 0; p < 4; ++p)                                   \
                    *(ull*)&rw[c * 32 + 2 * p] = acc[c][p];                   \
        }                                                                     \
    }

// ---- flag release: orders all prior stores --------------------------------
#define RELEASE(VAL)                                                          \
    if (tid == 0) {                                                           \
        asm volatile("st.release.gpu.global.u32 [%0], %1;"                    \
                     :: "l"(&g_flag[bh][cg * 8]), "r"(VAL) : "memory");       \
    }

// ---- owner sum + tanh + stores (owner: c = w, b = l) ----------------------
#define EPILOGUE(BIAS, BUF)                                                   \
    {                                                                         \
        float s = 0.f;                                                        \
        _Pragma("unroll")                                                     \
        for (int j = 0; j < 8; ++j) s += red[j * 512 + w * 32 + l];           \
        float h = tanhf(s + (BIAS));                                          \
        g_ht[BUF][cg * 16 + w][bh * 32 + l] = h;                              \
        C_f[w * CF_STRIDE + l] = h;                                           \
    }

    // ======================= tau = 0 prologue ==============================
    {
#pragma unroll
        for (int c = 0; c < 4; ++c)
#pragma unroll
            for (int p = 0; p < 4; ++p) acc[c][p] = 0ull;
        KLOOP(&g_xt[0][kbase][bB], wrow0);
        REDUCE_TO_SMEM();
        __syncthreads();
        EPILOGUE(bWc, 0);
        __syncthreads();
        RELEASE(base_r + 1u);
        o9[0] = C_f[c9 * CF_STRIDE + b9];
    }

    // ======================= main loop tau = 1..511 ========================
    for (int tau = 1; tau < T_; ++tau) {
        // phase X: acc = W x[:,tau,:] partials (no barrier dependency;
        // overlaps the whole inter-block flag window)
#pragma unroll
        for (int c = 0; c < 4; ++c)
#pragma unroll
            for (int p = 0; p < 4; ++p) acc[c][p] = 0ull;
        KLOOP(&g_xt[tau][kbase][bB], wrow0);

        // wait: all 64 peer flags must reach base+tau (h_{tau-1} released)
        {
            const unsigned tgt = base_r + (unsigned)tau;
            if (tid < GROUP_BLOCKS) {
                const unsigned* fp = &g_flag[bh][tid * 8];
                unsigned v;
                do {
                    asm volatile("ld.acquire.gpu.global.u32 %0, [%1];"
                                 : "=r"(v) : "l"(fp) : "memory");
                } while ((int)(v - tgt) < 0);
            }
            __syncthreads();               // S1: acquire broadcast + red reuse
        }

        // phase H: acc += U h_{tau-1} (same k-partition -> merged reduce)
        KLOOP(&g_ht[(tau - 1) & 1][kbase][bB], urow0);

        REDUCE_TO_SMEM();
        __syncthreads();                   // S2
        EPILOGUE(bSc, tau & 1);
        __syncthreads();                   // S3: g_ht + C_f visible

        // release ASAP (next step's enabling event)
        if (tau < T_ - 1) { RELEASE(base_r + (unsigned)tau + 1u); }

        // coalesced out1 (+out2) store, off the critical path
        float hv = C_f[c9 * CF_STRIDE + b9];
        o9[(size_t)tau * H_] = hv;
        if (tau == T_ - 1)
            out[(size_t)M_ * H_ + (size_t)(bh * 32 + b9) * H_ + cg * 16 + c9] = hv;
    }

#undef KLOOP
#undef REDUCE_TO_SMEM
#undef RELEASE
#undef EPILOGUE
}

// ---------------------------------------------------------------------------
// Launch
// ---------------------------------------------------------------------------
extern "C" void kernel_launch(void* const* d_in, const int* in_sizes, int n_in,
                              void* d_out, int out_size) {
    const float* x  = (const float*)d_in[0];   // [B,T,I]
    const float* W  = (const float*)d_in[1];   // [H,I]
    const float* bW = (const float*)d_in[2];   // [H]
    const float* U  = (const float*)d_in[3];   // [H,H]
    const float* bU = (const float*)d_in[4];   // [H]
    float* out = (float*)d_out;                // out1 [B*T*H] ++ out2 [B*H]

    dim3 tb(32, 8);
    dim3 tg(I_ / 32, B_ / 32, T_);   // (32, 2, 512)
    transpose_x_kernel<<<tg, tb>>>(x);

    cudaFuncSetAttribute(scan_kernel, cudaFuncAttributeMaxDynamicSharedMemorySize,
                         (int)SCAN_SMEM);
    scan_kernel<<<SCAN_BLOCKS, NTHREADS, SCAN_SMEM>>>(out, U, bU, W, bW);
}

// round 16
// speedup vs baseline: 1.2128x; 1.2128x over previous
#include <cuda_runtime.h>
#include <math.h>

#define B_  64
#define T_  512
#define I_  1024
#define H_  1024
#define M_  (B_*T_)

typedef unsigned long long ull;

// ---------------------------------------------------------------------------
// f32x2 packed helpers (sm_103a FFMA2/FADD2 — only reachable via PTX)
// ---------------------------------------------------------------------------
__device__ __forceinline__ ull ffma2(ull a, ull b, ull c) {
    ull d;
    asm("fma.rn.f32x2 %0, %1, %2, %3;" : "=l"(d) : "l"(a), "l"(b), "l"(c));
    return d;
}
__device__ __forceinline__ ull fadd2(ull a, ull b) {
    ull d;
    asm("add.rn.f32x2 %0, %1, %2;" : "=l"(d) : "l"(a), "l"(b));
    return d;
}
__device__ __forceinline__ ull splat2(float x) {
    ull r;
    asm("mov.b64 %0, {%1, %1};" : "=l"(r) : "f"(x));
    return r;
}

// ---------------------------------------------------------------------------
// Scratch (device globals — no allocation allowed)
// ---------------------------------------------------------------------------
__device__ float g_xt[T_][I_][B_];     // transposed x: [t][k][b]  (128 MB)
__device__ float g_ht[2][H_][B_];      // transposed h double buffer [buf][k][b]
__device__ unsigned g_flag[2][64 * 8]; // per-block progress flags (32B apart),
                                       // monotonic across graph replays

#define SCAN_BLOCKS  128
#define GROUP_BLOCKS 64
#define NTHREADS     512

// ---------------------------------------------------------------------------
// Kernel T: transpose x[b][t][i] -> g_xt[t][i][b]. 32x32 tiles.
// ---------------------------------------------------------------------------
__global__ __launch_bounds__(256)
void transpose_x_kernel(const float* __restrict__ x) {
    __shared__ float tile[32][33];
    const int tx = threadIdx.x;
    const int ty = threadIdx.y;
    const int i0 = blockIdx.x * 32;
    const int b0 = blockIdx.y * 32;
    const int t  = blockIdx.z;

#pragma unroll
    for (int r = ty; r < 32; r += 8)
        tile[r][tx] = x[(size_t)(b0 + r) * T_ * I_ + (size_t)t * I_ + i0 + tx];
    __syncthreads();
#pragma unroll
    for (int r = ty; r < 32; r += 8)
        g_xt[t][i0 + r][b0 + tx] = tile[tx][r];
}

// ---------------------------------------------------------------------------
// Kernel S: fused persistent scan — 512 threads, 16-WAY WARP-EXCLUSIVE k
// split (no cross-warp h duplication; R14's regression cause), merged X/H
// accumulation, distributed release/acquire flags.
//
// 128 blocks, 1/SM. Block (bh, cg): batches [bh*32,+32), cols [cg*16,+16).
// Warp w (16): k-slice [w*64,+64) — each k row loaded by exactly ONE warp.
// Lane l = k2*16 + cgl*8 + bg:
//   k2  (l>>4)    : 32/32 split of the warp's k-slice (merged by 1 shfl)
//   cgl ((l>>3)&1): col half (8 cols) — U broadcast in-warp (free)
//   bg  (l&7)     : 4-batch group (one LDG.128)
// Lane tile: 8c x 4b = 16 f32x2 accumulators.
//
// U_t/W_t: [k][16] stride-16 with per-row quad rotation
// phys_quad = (quad + (k>>5)) & 3; a lane's slice has (k>>5) = 2w+k2 =
// loop-invariant, so rotated addresses are constant per lane.
//
// Per step tau (one reduction):
//   X-kloop (acc = W x_tau, barrier-independent) -> flag wait -> H-kloop
//   (acc += U h_{tau-1}) -> shfl(k2) + smem(16w) reduce -> owner thread
//   (col=w, batch=l) 16-way sum + tanh -> g_ht + C_f -> release -> out1.
// ---------------------------------------------------------------------------
#define KT_STRIDE 16
#define KT_FLOATS (H_ * KT_STRIDE)                  // 16384 floats = 64 KB
#define RED_OFF   (2 * KT_FLOATS)                   // 32768
#define RED_FLOATS (16 * 512)                       // 32 KB
#define CF_OFF    (RED_OFF + RED_FLOATS)
#define CF_STRIDE 33
#define CF_FLOATS (16 * CF_STRIDE + 16)
#define BASE_OFF  (CF_OFF + CF_FLOATS)
#define SCAN_SMEM ((BASE_OFF + 8) * sizeof(float))  // ~162 KB

__global__ __launch_bounds__(NTHREADS, 1)
void scan_kernel(float* __restrict__ out, const float* __restrict__ U,
                 const float* __restrict__ bU, const float* __restrict__ W,
                 const float* __restrict__ bW) {
    extern __shared__ float smem[];
    float* U_t = smem;                  // [1024][16] quad-rotated
    float* W_t = smem + KT_FLOATS;      // [1024][16] quad-rotated
    float* red = smem + RED_OFF;        // [16][512]  [w][col*32+batch]
    float* C_f = smem + CF_OFF;         // [16][33]

    const int tid = threadIdx.x;
    const int l   = tid & 31;
    const int w   = tid >> 5;            // 0..15
    const int bh  = blockIdx.x & 1;
    const int cg  = blockIdx.x >> 1;     // 0..63
    const int k2  = l >> 4;              // 0..1
    const int cgl = (l >> 3) & 1;        // 0..1 (col half)
    const int bg  = l & 7;               // 0..7 (4-batch group)
    const int kbase = w * 64 + k2 * 32;
    const int rot   = kbase >> 5;        // = 2w + k2, loop-invariant
    const int q0 = ((cgl * 2 + 0 + rot) & 3) * 4;   // phys offset, col quad 0
    const int q1 = ((cgl * 2 + 1 + rot) & 3) * 4;   // phys offset, col quad 1

    // entry: read my OWN flag (only I write it) -> replay-safe base
    if (tid == 0) {
        unsigned v;
        asm volatile("ld.acquire.gpu.global.u32 %0, [%1];"
                     : "=r"(v) : "l"(&g_flag[bh][cg * 8]) : "memory");
        *(unsigned*)&smem[BASE_OFF] = v;
    }

    // one-time: transpose U/W slices into quad-rotated smem layout
    for (int idx = tid; idx < 16 * H_; idx += NTHREADS) {
        int c = idx >> 10;                // 0..15 (logical col)
        int k = idx & (H_ - 1);
        int pc = ((((c >> 2) + (k >> 5)) & 3) << 2) | (c & 3);
        U_t[k * KT_STRIDE + pc] = U[(size_t)(cg * 16 + c) * H_ + k];
        W_t[k * KT_STRIDE + pc] = W[(size_t)(cg * 16 + c) * I_ + k];
    }
    // owner thread (col = w, batch = l) bias
    const float bWc = bW[cg * 16 + w];
    const float bSc = bWc + bU[cg * 16 + w];
    __syncthreads();
    const unsigned base_r = *(const unsigned*)&smem[BASE_OFF];

    const float* urow0 = U_t + kbase * KT_STRIDE;
    const float* wrow0 = W_t + kbase * KT_STRIDE;
    const int bB = bh * 32 + bg * 4;     // lane's 4-batch base
    // out-store mapping
    const int b9 = tid >> 4;             // 0..31
    const int c9 = tid & 15;             // 0..15
    float* o9 = out + (size_t)(bh * 32 + b9) * T_ * H_ + cg * 16 + c9;

    ull acc[8][2];

// ---- macro: accumulate one 32-row k-slice matvec into acc -----------------
#define KLOOP(SRCROW, UWROW)                                                  \
    {                                                                         \
        const float* srow_ = (SRCROW);                                        \
        const float* mrow_ = (UWROW);                                         \
        _Pragma("unroll 8")                                                   \
        for (int i = 0; i < 32; ++i) {                                        \
            ulonglong2 hA = __ldcg((const ulonglong2*)(srow_ + i * B_));      \
            float4 u0 = *(const float4*)(mrow_ + i * KT_STRIDE + q0);         \
            float4 u1 = *(const float4*)(mrow_ + i * KT_STRIDE + q1);         \
            float uf[8] = {u0.x, u0.y, u0.z, u0.w, u1.x, u1.y, u1.z, u1.w};   \
            _Pragma("unroll")                                                 \
            for (int c = 0; c < 8; ++c) {                                     \
                ull s = splat2(uf[c]);                                        \
                acc[c][0] = ffma2(hA.x, s, acc[c][0]);                        \
                acc[c][1] = ffma2(hA.y, s, acc[c][1]);                        \
            }                                                                 \
        }                                                                     \
    }

// ---- macro: k2 butterfly + smem partials ([w][col*32+batch]) --------------
#define REDUCE_TO_SMEM()                                                      \
    {                                                                         \
        _Pragma("unroll")                                                     \
        for (int c = 0; c < 8; ++c)                                           \
            _Pragma("unroll")                                                 \
            for (int p = 0; p < 2; ++p)                                       \
                acc[c][p] = fadd2(acc[c][p],                                  \
                    __shfl_xor_sync(0xffffffffu, acc[c][p], 16));             \
        if (l < 16) {                                                         \
            float* rw = red + w * 512 + cgl * 256 + bg * 4;                   \
            _Pragma("unroll")                                                 \
            for (int c = 0; c < 8; ++c)                                       \
                _Pragma("unroll")                                             \
                for (int p = 0; p < 2; ++p)                                   \
                    *(ull*)&rw[c * 32 + 2 * p] = acc[c][p];                   \
        }                                                                     \
    }

// ---- flag release: orders all prior stores --------------------------------
#define RELEASE(VAL)                                                          \
    if (tid == 0) {                                                           \
        asm volatile("st.release.gpu.global.u32 [%0], %1;"                    \
                     :: "l"(&g_flag[bh][cg * 8]), "r"(VAL) : "memory");       \
    }

// ---- owner sum + tanh + stores (owner: col = w, batch = l) ----------------
#define EPILOGUE(BIAS, BUF)                                                   \
    {                                                                         \
        float s = 0.f;                                                        \
        _Pragma("unroll")                                                     \
        for (int j = 0; j < 16; ++j) s += red[j * 512 + w * 32 + l];          \
        float h = tanhf(s + (BIAS));                                          \
        g_ht[BUF][cg * 16 + w][bh * 32 + l] = h;                              \
        C_f[w * CF_STRIDE + l] = h;                                           \
    }

    // ======================= tau = 0 prologue ==============================
    {
#pragma unroll
        for (int c = 0; c < 8; ++c) { acc[c][0] = 0ull; acc[c][1] = 0ull; }
        KLOOP(&g_xt[0][kbase][bB], wrow0);
        REDUCE_TO_SMEM();
        __syncthreads();
        EPILOGUE(bWc, 0);
        __syncthreads();
        RELEASE(base_r + 1u);
        o9[0] = C_f[c9 * CF_STRIDE + b9];
    }

    // ======================= main loop tau = 1..511 ========================
    for (int tau = 1; tau < T_; ++tau) {
        // phase X: acc = W x[:,tau,:] partials (no barrier dependency;
        // overlaps the whole inter-block flag window)
#pragma unroll
        for (int c = 0; c < 8; ++c) { acc[c][0] = 0ull; acc[c][1] = 0ull; }
        KLOOP(&g_xt[tau][kbase][bB], wrow0);

        // wait: all 64 peer flags must reach base+tau (h_{tau-1} released)
        {
            const unsigned tgt = base_r + (unsigned)tau;
            if (tid < GROUP_BLOCKS) {
                const unsigned* fp = &g_flag[bh][tid * 8];
                unsigned v;
                do {
                    asm volatile("ld.acquire.gpu.global.u32 %0, [%1];"
                                 : "=r"(v) : "l"(fp) : "memory");
                } while ((int)(v - tgt) < 0);
            }
            __syncthreads();               // S1: acquire broadcast + red reuse
        }

        // phase H: acc += U h_{tau-1} (same k-partition -> merged reduce)
        KLOOP(&g_ht[(tau - 1) & 1][kbase][bB], urow0);

        REDUCE_TO_SMEM();
        __syncthreads();                   // S2
        EPILOGUE(bSc, tau & 1);
        __syncthreads();                   // S3: g_ht + C_f visible

        // release ASAP (next step's enabling event)
        if (tau < T_ - 1) { RELEASE(base_r + (unsigned)tau + 1u); }

        // coalesced out1 (+out2) store, off the critical path
        float hv = C_f[c9 * CF_STRIDE + b9];
        o9[(size_t)tau * H_] = hv;
        if (tau == T_ - 1)
            out[(size_t)M_ * H_ + (size_t)(bh * 32 + b9) * H_ + cg * 16 + c9] = hv;
    }

#undef KLOOP
#undef REDUCE_TO_SMEM
#undef RELEASE
#undef EPILOGUE
}

// ---------------------------------------------------------------------------
// Launch
// ---------------------------------------------------------------------------
extern "C" void kernel_launch(void* const* d_in, const int* in_sizes, int n_in,
                              void* d_out, int out_size) {
    const float* x  = (const float*)d_in[0];   // [B,T,I]
    const float* W  = (const float*)d_in[1];   // [H,I]
    const float* bW = (const float*)d_in[2];   // [H]
    const float* U  = (const float*)d_in[3];   // [H,H]
    const float* bU = (const float*)d_in[4];   // [H]
    float* out = (float*)d_out;                // out1 [B*T*H] ++ out2 [B*H]

    dim3 tb(32, 8);
    dim3 tg(I_ / 32, B_ / 32, T_);   // (32, 2, 512)
    transpose_x_kernel<<<tg, tb>>>(x);

    cudaFuncSetAttribute(scan_kernel, cudaFuncAttributeMaxDynamicSharedMemorySize,
                         (int)SCAN_SMEM);
    scan_kernel<<<SCAN_BLOCKS, NTHREADS, SCAN_SMEM>>>(out, U, bU, W, bW);
}